// round 10
// baseline (speedup 1.0000x reference)
#include <cuda_runtime.h>
#include <cuda_bf16.h>
#include <math.h>
#include <stdint.h>

#define NN 50000
#define EE 800000
#define DIN 256
#define DH 128
#define DOUT 128

// ---------------- scratch (device globals; no allocation allowed) -------------
__device__ __nv_bfloat16 g_w2_hi[512 * DH];
__device__ __nv_bfloat16 g_w2_lo[512 * DH];
__device__ float g_b2[512];
__device__ float g_q[(size_t)NN * DH];              // 25.6 MB fp32 (per-warp read)
__device__ float g_kv[(size_t)NN * 192];            // 38.4 MB: per node [k bf16 256B | v fp32 512B]
__device__ float g_skip[(size_t)NN * DH];           // 25.6 MB fp32 (per-warp read)
__device__ int   g_deg[NN];
__device__ int   g_off[NN + 1];
__device__ int   g_cur[NN];
__device__ int   g_src[EE];
__device__ int   g_part[256];
__device__ int   g_is64;

// ---------------- helpers ------------------------------------------------------
__device__ __forceinline__ uint32_t smem_u32(const void* p) {
    uint32_t a;
    asm("{ .reg .u64 t; cvta.to.shared.u64 t, %1; cvt.u32.u64 %0, t; }" : "=r"(a) : "l"(p));
    return a;
}
__device__ __forceinline__ uint32_t pack_hi2(float a, float b) {
    __nv_bfloat162 t = __floats2bfloat162_rn(a, b);
    return *(uint32_t*)&t;
}
__device__ __forceinline__ uint32_t pack_lo2(float a, float b) {
    float ra = a - __bfloat162float(__float2bfloat16_rn(a));
    float rb = b - __bfloat162float(__float2bfloat16_rn(b));
    __nv_bfloat162 t = __floats2bfloat162_rn(ra, rb);
    return *(uint32_t*)&t;
}
__device__ __forceinline__ void mma_bf16(float d[4], const uint32_t a[4], const uint32_t b[2]) {
    asm volatile(
        "mma.sync.aligned.m16n8k16.row.col.f32.bf16.bf16.f32 "
        "{%0,%1,%2,%3}, {%4,%5,%6,%7}, {%8,%9}, {%0,%1,%2,%3};"
        : "+f"(d[0]), "+f"(d[1]), "+f"(d[2]), "+f"(d[3])
        : "r"(a[0]), "r"(a[1]), "r"(a[2]), "r"(a[3]), "r"(b[0]), "r"(b[1]));
}
__device__ __forceinline__ void ldsm4(uint32_t r[4], uint32_t addr) {
    asm volatile("ldmatrix.sync.aligned.m8n8.x4.shared.b16 {%0,%1,%2,%3}, [%4];"
                 : "=r"(r[0]), "=r"(r[1]), "=r"(r[2]), "=r"(r[3]) : "r"(addr));
}

// ---------------- fused GEMM: x -> h (SMEM) -> q/kv/skip ------------------------
#define PAD1 40
#define PH   136
#define OFF_ASH 0
#define OFF_ASL 5120
#define OFF_BSH 10240
#define OFF_BSL 15360
#define OFF_HH  20480
#define OFF_HL  37888
#define OFF_W2H 0
#define OFF_W2L 8704
#define SMEM_ELEMS 55296   // 110592 bytes

__global__ __launch_bounds__(256) void fused_kernel(const float* __restrict__ x,
                                                    const float* __restrict__ w1,
                                                    const float* __restrict__ bias1)
{
    extern __shared__ __nv_bfloat16 sm[];
    const int tid = threadIdx.x, lane = tid & 31, wid = tid >> 5;
    const int warpM = wid & 3, warpN = wid >> 2;
    const int m0 = blockIdx.x * 128;
    const uint32_t sb = smem_u32(sm);

    const int aRowSel = lane & 15;
    const int aColSel = (lane >> 4) << 3;
    const int bRowSel = ((lane >> 4) << 3) + (lane & 7);
    const int bColSel = ((lane >> 3) & 1) << 3;

    // ---------------- phase 1: K=256 mainloop -----------------------------------
    float acc[2][8][4];
#pragma unroll
    for (int mt = 0; mt < 2; mt++)
#pragma unroll
        for (int nt = 0; nt < 8; nt++)
#pragma unroll
            for (int r = 0; r < 4; r++) acc[mt][nt][r] = 0.f;

    float4 rA[4], rB[4];
    const int arow = tid >> 3, ac4 = tid & 7;
#pragma unroll
    for (int it = 0; it < 4; it++) {
        int row = arow + it * 32;
        int grow = m0 + row;
        rA[it] = (grow < NN) ? *(const float4*)(x + (size_t)grow * DIN + ac4 * 4)
                             : make_float4(0.f, 0.f, 0.f, 0.f);
        rB[it] = *(const float4*)(w1 + (size_t)row * DIN + ac4 * 4);
    }

    for (int k0 = 0; k0 < DIN; k0 += 32) {
#pragma unroll
        for (int it = 0; it < 4; it++) {
            int row = arow + it * 32;
            float4 v = rA[it];
            *(uint2*)(sm + OFF_ASH + row * PAD1 + ac4 * 4) = make_uint2(pack_hi2(v.x, v.y), pack_hi2(v.z, v.w));
            *(uint2*)(sm + OFF_ASL + row * PAD1 + ac4 * 4) = make_uint2(pack_lo2(v.x, v.y), pack_lo2(v.z, v.w));
            v = rB[it];
            *(uint2*)(sm + OFF_BSH + row * PAD1 + ac4 * 4) = make_uint2(pack_hi2(v.x, v.y), pack_hi2(v.z, v.w));
            *(uint2*)(sm + OFF_BSL + row * PAD1 + ac4 * 4) = make_uint2(pack_lo2(v.x, v.y), pack_lo2(v.z, v.w));
        }
        __syncthreads();

        if (k0 + 32 < DIN) {
#pragma unroll
            for (int it = 0; it < 4; it++) {
                int row = arow + it * 32;
                int grow = m0 + row;
                rA[it] = (grow < NN) ? *(const float4*)(x + (size_t)grow * DIN + k0 + 32 + ac4 * 4)
                                     : make_float4(0.f, 0.f, 0.f, 0.f);
                rB[it] = *(const float4*)(w1 + (size_t)row * DIN + k0 + 32 + ac4 * 4);
            }
        }

#pragma unroll
        for (int ks = 0; ks < 2; ks++) {
            const int kb = ks * 16;
            uint32_t ah[2][4], al[2][4];
#pragma unroll
            for (int mt = 0; mt < 2; mt++) {
                uint32_t a_addr = sb + 2 * (OFF_ASH + (warpM * 32 + mt * 16 + aRowSel) * PAD1 + kb + aColSel);
                ldsm4(ah[mt], a_addr);
                ldsm4(al[mt], a_addr + 2 * (OFF_ASL - OFF_ASH));
            }
#pragma unroll
            for (int p = 0; p < 4; p++) {
                uint32_t b_addr = sb + 2 * (OFF_BSH + (warpN * 64 + p * 16 + bRowSel) * PAD1 + kb + bColSel);
                uint32_t bh[4], bl[4];
                ldsm4(bh, b_addr);
                ldsm4(bl, b_addr + 2 * (OFF_BSL - OFF_BSH));
#pragma unroll
                for (int mt = 0; mt < 2; mt++) {
                    mma_bf16(acc[mt][2 * p],     ah[mt], bh);
                    mma_bf16(acc[mt][2 * p],     ah[mt], bl);
                    mma_bf16(acc[mt][2 * p],     al[mt], bh);
                    mma_bf16(acc[mt][2 * p + 1], ah[mt], bh + 2);
                    mma_bf16(acc[mt][2 * p + 1], ah[mt], bl + 2);
                    mma_bf16(acc[mt][2 * p + 1], al[mt], bh + 2);
                }
            }
        }
        __syncthreads();
    }

    // prefetch W2 chunk 0
    uint4 rWh[4], rWl[4];
    const int brow = tid >> 4, bchunk = tid & 15;
#pragma unroll
    for (int it = 0; it < 4; it++) {
        int row = brow + it * 16;
        rWh[it] = *(const uint4*)(g_w2_hi + (size_t)row * DH + bchunk * 8);
        rWl[it] = *(const uint4*)(g_w2_lo + (size_t)row * DH + bchunk * 8);
    }

    // h epilogue: bias + relu -> SMEM (bf16 hi/lo)
#pragma unroll
    for (int mt = 0; mt < 2; mt++) {
        int r0 = warpM * 32 + mt * 16 + (lane >> 2);
#pragma unroll
        for (int nt = 0; nt < 8; nt++) {
            int col = warpN * 64 + nt * 8 + 2 * (lane & 3);
            float b0 = bias1[col], b1 = bias1[col + 1];
            float v0 = fmaxf(acc[mt][nt][0] + b0, 0.f);
            float v1 = fmaxf(acc[mt][nt][1] + b1, 0.f);
            float v2 = fmaxf(acc[mt][nt][2] + b0, 0.f);
            float v3 = fmaxf(acc[mt][nt][3] + b1, 0.f);
            *(uint32_t*)(sm + OFF_HH + r0 * PH + col) = pack_hi2(v0, v1);
            *(uint32_t*)(sm + OFF_HL + r0 * PH + col) = pack_lo2(v0, v1);
            *(uint32_t*)(sm + OFF_HH + (r0 + 8) * PH + col) = pack_hi2(v2, v3);
            *(uint32_t*)(sm + OFF_HL + (r0 + 8) * PH + col) = pack_lo2(v2, v3);
        }
    }
    __syncthreads();

    // ---------------- phase 2: [q|k|v|skip] = h @ W2^T + b2 ----------------------
    // nc 0-1 -> g_q (fp32), nc 2-3 -> g_kv k-part (bf16),
    // nc 4-5 -> g_kv v-part (fp32), nc 6-7 -> g_skip
    for (int nc = 0; nc < 8; nc++) {
#pragma unroll
        for (int it = 0; it < 4; it++) {
            int row = brow + it * 16;
            *(uint4*)(sm + OFF_W2H + row * PH + bchunk * 8) = rWh[it];
            *(uint4*)(sm + OFF_W2L + row * PH + bchunk * 8) = rWl[it];
        }
        __syncthreads();

        if (nc + 1 < 8) {
#pragma unroll
            for (int it = 0; it < 4; it++) {
                int row = (nc + 1) * 64 + brow + it * 16;
                rWh[it] = *(const uint4*)(g_w2_hi + (size_t)row * DH + bchunk * 8);
                rWl[it] = *(const uint4*)(g_w2_lo + (size_t)row * DH + bchunk * 8);
            }
        }

        float a2[2][4][4];
#pragma unroll
        for (int mt = 0; mt < 2; mt++)
#pragma unroll
            for (int nt = 0; nt < 4; nt++)
#pragma unroll
                for (int r = 0; r < 4; r++) a2[mt][nt][r] = 0.f;

#pragma unroll
        for (int ks = 0; ks < 8; ks++) {
            const int kb = ks * 16;
            uint32_t ah[2][4], al[2][4];
#pragma unroll
            for (int mt = 0; mt < 2; mt++) {
                uint32_t a_addr = sb + 2 * (OFF_HH + (warpM * 32 + mt * 16 + aRowSel) * PH + kb + aColSel);
                ldsm4(ah[mt], a_addr);
                ldsm4(al[mt], a_addr + 2 * (OFF_HL - OFF_HH));
            }
#pragma unroll
            for (int p = 0; p < 2; p++) {
                uint32_t b_addr = sb + 2 * (OFF_W2H + (warpN * 32 + p * 16 + bRowSel) * PH + kb + bColSel);
                uint32_t bh[4], bl[4];
                ldsm4(bh, b_addr);
                ldsm4(bl, b_addr + 2 * (OFF_W2L - OFF_W2H));
#pragma unroll
                for (int mt = 0; mt < 2; mt++) {
                    mma_bf16(a2[mt][2 * p],     ah[mt], bh);
                    mma_bf16(a2[mt][2 * p],     ah[mt], bl);
                    mma_bf16(a2[mt][2 * p],     al[mt], bh);
                    mma_bf16(a2[mt][2 * p + 1], ah[mt], bh + 2);
                    mma_bf16(a2[mt][2 * p + 1], ah[mt], bl + 2);
                    mma_bf16(a2[mt][2 * p + 1], al[mt], bh + 2);
                }
            }
        }

        // routed epilogue
        const int sect = nc >> 1;              // 0:q 1:k 2:v 3:skip
#pragma unroll
        for (int mt = 0; mt < 2; mt++) {
            int r0 = m0 + warpM * 32 + mt * 16 + (lane >> 2);
#pragma unroll
            for (int nt = 0; nt < 4; nt++) {
                int gcol = nc * 64 + warpN * 32 + nt * 8 + 2 * (lane & 3);
                int col = gcol & 127;          // column within the 128-wide section
                float b0 = g_b2[gcol], b1 = g_b2[gcol + 1];
                float v0 = a2[mt][nt][0] + b0, v1 = a2[mt][nt][1] + b1;
                float v2 = a2[mt][nt][2] + b0, v3 = a2[mt][nt][3] + b1;
                if (sect == 1) {               // k -> bf16, row offset 0 of g_kv
                    if (r0 < NN)
                        *(uint32_t*)((char*)(g_kv + (size_t)r0 * 192) + col * 2) = pack_hi2(v0, v1);
                    if (r0 + 8 < NN)
                        *(uint32_t*)((char*)(g_kv + (size_t)(r0 + 8) * 192) + col * 2) = pack_hi2(v2, v3);
                } else if (sect == 2) {        // v -> fp32, row offset 64 floats
                    if (r0 < NN)     { float2 o = {v0, v1}; *(float2*)(g_kv + (size_t)r0 * 192 + 64 + col) = o; }
                    if (r0 + 8 < NN) { float2 o = {v2, v3}; *(float2*)(g_kv + (size_t)(r0 + 8) * 192 + 64 + col) = o; }
                } else {
                    float* dst = (sect == 0) ? g_q : g_skip;
                    if (r0 < NN)     { float2 o = {v0, v1}; *(float2*)(dst + (size_t)r0 * DH + col) = o; }
                    if (r0 + 8 < NN) { float2 o = {v2, v3}; *(float2*)(dst + (size_t)(r0 + 8) * DH + col) = o; }
                }
            }
        }
        __syncthreads();
    }
}

// ---------------- W2 pack + convert (fp32 -> bf16 hi/lo) -----------------------
__global__ void conv_w2_kernel(const float* __restrict__ wq, const float* __restrict__ bq,
                               const float* __restrict__ wk, const float* __restrict__ bk,
                               const float* __restrict__ wv, const float* __restrict__ bv,
                               const float* __restrict__ ws, const float* __restrict__ bs)
{
    int i = blockIdx.x * blockDim.x + threadIdx.x;
    if (i < 512 * DH / 2) {
        int row = (2 * i) / DH;
        int kp  = i % (DH / 2);
        const float* w = (row < 128) ? wq : (row < 256) ? wk : (row < 384) ? wv : ws;
        const float2 v = ((const float2*)(w + (row & 127) * DH))[kp];
        ((uint32_t*)g_w2_hi)[i] = pack_hi2(v.x, v.y);
        ((uint32_t*)g_w2_lo)[i] = pack_lo2(v.x, v.y);
    }
    if (i < 512) {
        const float* b = (i < 128) ? bq : (i < 256) ? bk : (i < 384) ? bv : bs;
        g_b2[i] = b[i & 127];
    }
}

// ---------------- edge dtype detection ----------------------------------------
__global__ void detect_dtype_kernel(const int* __restrict__ ei_raw)
{
    __shared__ int nz;
    if (threadIdx.x == 0) nz = 0;
    __syncthreads();
    int w = ei_raw[2 * threadIdx.x + 1];
    if (w != 0) atomicAdd(&nz, 1);
    __syncthreads();
    if (threadIdx.x == 0) g_is64 = (nz == 0) ? 1 : 0;
}

// ---------------- CSR build ----------------------------------------------------
__device__ __forceinline__ int load_edge(const int* ei_raw, int e, int half)
{
    if (g_is64) return ei_raw[2 * (half * EE + e)];
    else        return ei_raw[half * EE + e];
}

__global__ void zero_deg_kernel()
{
    int i = blockIdx.x * blockDim.x + threadIdx.x;
    if (i < NN) g_deg[i] = 0;
}

__global__ void count_deg_kernel(const int* __restrict__ ei_raw)
{
    int e = blockIdx.x * blockDim.x + threadIdx.x;
    if (e < EE) {
        int dst = load_edge(ei_raw, e, 1);
        if (dst >= 0 && dst < NN) atomicAdd(&g_deg[dst], 1);
    }
}

#define SCAN_BLKS ((NN + 255) / 256)
__global__ void scan1_kernel()
{
    __shared__ int sm[256];
    int i = blockIdx.x * 256 + threadIdx.x;
    sm[threadIdx.x] = (i < NN) ? g_deg[i] : 0;
    __syncthreads();
    for (int o = 128; o > 0; o >>= 1) {
        if (threadIdx.x < o) sm[threadIdx.x] += sm[threadIdx.x + o];
        __syncthreads();
    }
    if (threadIdx.x == 0) g_part[blockIdx.x] = sm[0];
}

__global__ void scan2_kernel()
{
    __shared__ int sm[256];
    int t = threadIdx.x;
    int v = (t < SCAN_BLKS) ? g_part[t] : 0;
    sm[t] = v;
    __syncthreads();
    for (int o = 1; o < 256; o <<= 1) {
        int u = (t >= o) ? sm[t - o] : 0;
        __syncthreads();
        sm[t] += u;
        __syncthreads();
    }
    if (t < SCAN_BLKS) g_part[t] = sm[t] - v;
    if (t == 255) g_off[NN] = sm[255];
}

__global__ void scan3_kernel()
{
    __shared__ int sm[256];
    int i = blockIdx.x * 256 + threadIdx.x;
    int v = (i < NN) ? g_deg[i] : 0;
    sm[threadIdx.x] = v;
    __syncthreads();
    for (int o = 1; o < 256; o <<= 1) {
        int u = (threadIdx.x >= o) ? sm[threadIdx.x - o] : 0;
        __syncthreads();
        sm[threadIdx.x] += u;
        __syncthreads();
    }
    if (i < NN) {
        int off = g_part[blockIdx.x] + sm[threadIdx.x] - v;
        g_off[i] = off;
        g_cur[i] = off;
    }
}

__global__ void scatter_kernel(const int* __restrict__ ei_raw)
{
    int e = blockIdx.x * blockDim.x + threadIdx.x;
    if (e < EE) {
        int src = load_edge(ei_raw, e, 0);
        int dst = load_edge(ei_raw, e, 1);
        if (src >= 0 && src < NN && dst >= 0 && dst < NN) {
            int pos = atomicAdd(&g_cur[dst], 1);
            if (pos >= 0 && pos < EE) g_src[pos] = src;
        }
    }
}

// ---------------- per-node online-softmax aggregation: one warp per node -------
// k (bf16) and v (fp32) interleaved per node row (768B) -> single-row gather.
__global__ void agg_kernel(float* __restrict__ out)
{
    int warp = (blockIdx.x * blockDim.x + threadIdx.x) >> 5;
    int lane = threadIdx.x & 31;
    if (warp >= NN) return;

    const float4 q = *(const float4*)(g_q + (size_t)warp * DH + 4 * lane);

    const int s = g_off[warp];
    const int e = g_off[warp + 1];

    const float scale = 0.088388347648318447f;  // 1/sqrt(128)
    float m = -INFINITY, l = 0.f;
    float4 acc = make_float4(0.f, 0.f, 0.f, 0.f);

    if (e > s) {
        int src = g_src[s];
        const float* base = g_kv + (size_t)src * 192;
        uint2 kp = *(const uint2*)((const char*)base + 8 * lane);
        float4 vv = *(const float4*)(base + 64 + 4 * lane);

        for (int j = s; j < e; j++) {
            uint2 kp_n;
            float4 vv_n;
            if (j + 1 < e) {
                int src_n = g_src[j + 1];
                const float* base_n = g_kv + (size_t)src_n * 192;
                kp_n = *(const uint2*)((const char*)base_n + 8 * lane);
                vv_n = *(const float4*)(base_n + 64 + 4 * lane);
            }

            float2 k01 = __bfloat1622float2(*(__nv_bfloat162*)&kp.x);
            float2 k23 = __bfloat1622float2(*(__nv_bfloat162*)&kp.y);
            float d = q.x * k01.x + q.y * k01.y + q.z * k23.x + q.w * k23.y;
            d += __shfl_xor_sync(0xffffffffu, d, 16);
            d += __shfl_xor_sync(0xffffffffu, d, 8);
            d += __shfl_xor_sync(0xffffffffu, d, 4);
            d += __shfl_xor_sync(0xffffffffu, d, 2);
            d += __shfl_xor_sync(0xffffffffu, d, 1);
            d *= scale;

            float newm = fmaxf(m, d);
            float fac = __expf(m - newm);
            float p   = __expf(d - newm);
            l = l * fac + p;

            acc.x = acc.x * fac + p * vv.x;
            acc.y = acc.y * fac + p * vv.y;
            acc.z = acc.z * fac + p * vv.z;
            acc.w = acc.w * fac + p * vv.w;
            m = newm;

            kp = kp_n;
            vv = vv_n;
        }
    }

    const float4 sk = *(const float4*)(g_skip + (size_t)warp * DH + 4 * lane);
    float inv = (e > s) ? (1.f / l) : 0.f;
    float4 o;
    o.x = acc.x * inv + sk.x;
    o.y = acc.y * inv + sk.y;
    o.z = acc.z * inv + sk.z;
    o.w = acc.w * inv + sk.w;
    *(float4*)(out + (size_t)warp * DOUT + 4 * lane) = o;
}

// ---------------- launch --------------------------------------------------------
extern "C" void kernel_launch(void* const* d_in, const int* in_sizes, int n_in,
                              void* d_out, int out_size)
{
    const float* x    = (const float*)d_in[0];
    const int*   ei   = (const int*)d_in[1];
    const float* W_fc = (const float*)d_in[2];
    const float* b_fc = (const float*)d_in[3];
    const float* W_q  = (const float*)d_in[4];
    const float* b_q  = (const float*)d_in[5];
    const float* W_k  = (const float*)d_in[6];
    const float* b_k  = (const float*)d_in[7];
    const float* W_v  = (const float*)d_in[8];
    const float* b_v  = (const float*)d_in[9];
    const float* W_s  = (const float*)d_in[10];
    const float* b_s  = (const float*)d_in[11];
    float* out = (float*)d_out;

    static cudaStream_t s_side = nullptr;
    static cudaEvent_t ev_fork = nullptr, ev_join = nullptr;
    if (!s_side) {
        cudaStreamCreateWithFlags(&s_side, cudaStreamNonBlocking);
        cudaEventCreateWithFlags(&ev_fork, cudaEventDisableTiming);
        cudaEventCreateWithFlags(&ev_join, cudaEventDisableTiming);
        cudaFuncSetAttribute(fused_kernel, cudaFuncAttributeMaxDynamicSharedMemorySize,
                             SMEM_ELEMS * 2);
    }

    detect_dtype_kernel<<<1, 256>>>(ei);
    cudaEventRecord(ev_fork, 0);
    cudaStreamWaitEvent(s_side, ev_fork, 0);

    // --- side stream: CSR build ---
    zero_deg_kernel<<<(NN + 255) / 256, 256, 0, s_side>>>();
    count_deg_kernel<<<(EE + 255) / 256, 256, 0, s_side>>>(ei);
    scan1_kernel<<<SCAN_BLKS, 256, 0, s_side>>>();
    scan2_kernel<<<1, 256, 0, s_side>>>();
    scan3_kernel<<<SCAN_BLKS, 256, 0, s_side>>>();
    scatter_kernel<<<(EE + 255) / 256, 256, 0, s_side>>>(ei);
    cudaEventRecord(ev_join, s_side);

    // --- main stream: W2 conversion + fused GEMM ---
    conv_w2_kernel<<<(512 * DH / 2 + 255) / 256, 256>>>(W_q, b_q, W_k, b_k, W_v, b_v, W_s, b_s);
    fused_kernel<<<(NN + 127) / 128, 256, SMEM_ELEMS * 2>>>(x, W_fc, b_fc);

    // join, then aggregate
    cudaStreamWaitEvent(0, ev_join, 0);
    agg_kernel<<<(NN * 32 + 255) / 256, 256>>>(out);
}

// round 11
// speedup vs baseline: 1.1381x; 1.1381x over previous
#include <cuda_runtime.h>
#include <cuda_bf16.h>
#include <math.h>
#include <stdint.h>

#define NN 50000
#define EE 800000
#define DIN 256
#define DH 128
#define DOUT 128

// ---------------- scratch (device globals; no allocation allowed) -------------
__device__ __nv_bfloat16 g_w2_hi[512 * DH];
__device__ __nv_bfloat16 g_w2_lo[512 * DH];
__device__ float g_b2[512];
__device__ float g_qkvs[(size_t)NN * 512];          // 102.4 MB : per node [q k v skip]
__device__ int   g_deg[NN];
__device__ int   g_off[NN + 1];
__device__ int   g_cur[NN];
__device__ int   g_src[EE];
__device__ int   g_part[256];
__device__ int   g_is64;

// ---------------- helpers ------------------------------------------------------
__device__ __forceinline__ uint32_t smem_u32(const void* p) {
    uint32_t a;
    asm("{ .reg .u64 t; cvta.to.shared.u64 t, %1; cvt.u32.u64 %0, t; }" : "=r"(a) : "l"(p));
    return a;
}
__device__ __forceinline__ uint32_t pack_hi2(float a, float b) {
    __nv_bfloat162 t = __floats2bfloat162_rn(a, b);
    return *(uint32_t*)&t;
}
__device__ __forceinline__ uint32_t pack_lo2(float a, float b) {
    float ra = a - __bfloat162float(__float2bfloat16_rn(a));
    float rb = b - __bfloat162float(__float2bfloat16_rn(b));
    __nv_bfloat162 t = __floats2bfloat162_rn(ra, rb);
    return *(uint32_t*)&t;
}
__device__ __forceinline__ void mma_bf16(float d[4], const uint32_t a[4], const uint32_t b[2]) {
    asm volatile(
        "mma.sync.aligned.m16n8k16.row.col.f32.bf16.bf16.f32 "
        "{%0,%1,%2,%3}, {%4,%5,%6,%7}, {%8,%9}, {%0,%1,%2,%3};"
        : "+f"(d[0]), "+f"(d[1]), "+f"(d[2]), "+f"(d[3])
        : "r"(a[0]), "r"(a[1]), "r"(a[2]), "r"(a[3]), "r"(b[0]), "r"(b[1]));
}
__device__ __forceinline__ void ldsm4(uint32_t r[4], uint32_t addr) {
    asm volatile("ldmatrix.sync.aligned.m8n8.x4.shared.b16 {%0,%1,%2,%3}, [%4];"
                 : "=r"(r[0]), "=r"(r[1]), "=r"(r[2]), "=r"(r[3]) : "r"(addr));
}

// ---------------- fused GEMM: x -> h (SMEM) -> qkvs -----------------------------
#define PAD1 40
#define PH   136
#define OFF_ASH 0
#define OFF_ASL 5120
#define OFF_BSH 10240
#define OFF_BSL 15360
#define OFF_HH  20480
#define OFF_HL  37888
#define OFF_W2H 0
#define OFF_W2L 8704
#define SMEM_ELEMS 55296   // 110592 bytes

__global__ __launch_bounds__(256) void fused_kernel(const float* __restrict__ x,
                                                    const float* __restrict__ w1,
                                                    const float* __restrict__ bias1)
{
    extern __shared__ __nv_bfloat16 sm[];
    const int tid = threadIdx.x, lane = tid & 31, wid = tid >> 5;
    const int warpM = wid & 3, warpN = wid >> 2;
    const int m0 = blockIdx.x * 128;
    const uint32_t sb = smem_u32(sm);

    const int aRowSel = lane & 15;
    const int aColSel = (lane >> 4) << 3;
    const int bRowSel = ((lane >> 4) << 3) + (lane & 7);
    const int bColSel = ((lane >> 3) & 1) << 3;

    // ---------------- phase 1: K=256 mainloop -----------------------------------
    float acc[2][8][4];
#pragma unroll
    for (int mt = 0; mt < 2; mt++)
#pragma unroll
        for (int nt = 0; nt < 8; nt++)
#pragma unroll
            for (int r = 0; r < 4; r++) acc[mt][nt][r] = 0.f;

    float4 rA[4], rB[4];
    const int arow = tid >> 3, ac4 = tid & 7;
#pragma unroll
    for (int it = 0; it < 4; it++) {
        int row = arow + it * 32;
        int grow = m0 + row;
        rA[it] = (grow < NN) ? *(const float4*)(x + (size_t)grow * DIN + ac4 * 4)
                             : make_float4(0.f, 0.f, 0.f, 0.f);
        rB[it] = *(const float4*)(w1 + (size_t)row * DIN + ac4 * 4);
    }

    for (int k0 = 0; k0 < DIN; k0 += 32) {
#pragma unroll
        for (int it = 0; it < 4; it++) {
            int row = arow + it * 32;
            float4 v = rA[it];
            *(uint2*)(sm + OFF_ASH + row * PAD1 + ac4 * 4) = make_uint2(pack_hi2(v.x, v.y), pack_hi2(v.z, v.w));
            *(uint2*)(sm + OFF_ASL + row * PAD1 + ac4 * 4) = make_uint2(pack_lo2(v.x, v.y), pack_lo2(v.z, v.w));
            v = rB[it];
            *(uint2*)(sm + OFF_BSH + row * PAD1 + ac4 * 4) = make_uint2(pack_hi2(v.x, v.y), pack_hi2(v.z, v.w));
            *(uint2*)(sm + OFF_BSL + row * PAD1 + ac4 * 4) = make_uint2(pack_lo2(v.x, v.y), pack_lo2(v.z, v.w));
        }
        __syncthreads();

        if (k0 + 32 < DIN) {
#pragma unroll
            for (int it = 0; it < 4; it++) {
                int row = arow + it * 32;
                int grow = m0 + row;
                rA[it] = (grow < NN) ? *(const float4*)(x + (size_t)grow * DIN + k0 + 32 + ac4 * 4)
                                     : make_float4(0.f, 0.f, 0.f, 0.f);
                rB[it] = *(const float4*)(w1 + (size_t)row * DIN + k0 + 32 + ac4 * 4);
            }
        }

#pragma unroll
        for (int ks = 0; ks < 2; ks++) {
            const int kb = ks * 16;
            uint32_t ah[2][4], al[2][4];
#pragma unroll
            for (int mt = 0; mt < 2; mt++) {
                uint32_t a_addr = sb + 2 * (OFF_ASH + (warpM * 32 + mt * 16 + aRowSel) * PAD1 + kb + aColSel);
                ldsm4(ah[mt], a_addr);
                ldsm4(al[mt], a_addr + 2 * (OFF_ASL - OFF_ASH));
            }
#pragma unroll
            for (int p = 0; p < 4; p++) {
                uint32_t b_addr = sb + 2 * (OFF_BSH + (warpN * 64 + p * 16 + bRowSel) * PAD1 + kb + bColSel);
                uint32_t bh[4], bl[4];
                ldsm4(bh, b_addr);
                ldsm4(bl, b_addr + 2 * (OFF_BSL - OFF_BSH));
#pragma unroll
                for (int mt = 0; mt < 2; mt++) {
                    mma_bf16(acc[mt][2 * p],     ah[mt], bh);
                    mma_bf16(acc[mt][2 * p],     ah[mt], bl);
                    mma_bf16(acc[mt][2 * p],     al[mt], bh);
                    mma_bf16(acc[mt][2 * p + 1], ah[mt], bh + 2);
                    mma_bf16(acc[mt][2 * p + 1], ah[mt], bl + 2);
                    mma_bf16(acc[mt][2 * p + 1], al[mt], bh + 2);
                }
            }
        }
        __syncthreads();
    }

    // prefetch W2 chunk 0 (overlaps h epilogue)
    uint4 rWh[4], rWl[4];
    const int brow = tid >> 4, bchunk = tid & 15;
#pragma unroll
    for (int it = 0; it < 4; it++) {
        int row = brow + it * 16;
        rWh[it] = *(const uint4*)(g_w2_hi + (size_t)row * DH + bchunk * 8);
        rWl[it] = *(const uint4*)(g_w2_lo + (size_t)row * DH + bchunk * 8);
    }

    // h epilogue: bias + relu -> SMEM (bf16 hi/lo)
#pragma unroll
    for (int mt = 0; mt < 2; mt++) {
        int r0 = warpM * 32 + mt * 16 + (lane >> 2);
#pragma unroll
        for (int nt = 0; nt < 8; nt++) {
            int col = warpN * 64 + nt * 8 + 2 * (lane & 3);
            float b0 = bias1[col], b1 = bias1[col + 1];
            float v0 = fmaxf(acc[mt][nt][0] + b0, 0.f);
            float v1 = fmaxf(acc[mt][nt][1] + b1, 0.f);
            float v2 = fmaxf(acc[mt][nt][2] + b0, 0.f);
            float v3 = fmaxf(acc[mt][nt][3] + b1, 0.f);
            *(uint32_t*)(sm + OFF_HH + r0 * PH + col) = pack_hi2(v0, v1);
            *(uint32_t*)(sm + OFF_HL + r0 * PH + col) = pack_lo2(v0, v1);
            *(uint32_t*)(sm + OFF_HH + (r0 + 8) * PH + col) = pack_hi2(v2, v3);
            *(uint32_t*)(sm + OFF_HL + (r0 + 8) * PH + col) = pack_lo2(v2, v3);
        }
    }
    __syncthreads();

    // ---------------- phase 2: qkvs = h @ W2^T + b2 ------------------------------
    for (int nc = 0; nc < 8; nc++) {
#pragma unroll
        for (int it = 0; it < 4; it++) {
            int row = brow + it * 16;
            *(uint4*)(sm + OFF_W2H + row * PH + bchunk * 8) = rWh[it];
            *(uint4*)(sm + OFF_W2L + row * PH + bchunk * 8) = rWl[it];
        }
        __syncthreads();

        if (nc + 1 < 8) {
#pragma unroll
            for (int it = 0; it < 4; it++) {
                int row = (nc + 1) * 64 + brow + it * 16;
                rWh[it] = *(const uint4*)(g_w2_hi + (size_t)row * DH + bchunk * 8);
                rWl[it] = *(const uint4*)(g_w2_lo + (size_t)row * DH + bchunk * 8);
            }
        }

        float a2[2][4][4];
#pragma unroll
        for (int mt = 0; mt < 2; mt++)
#pragma unroll
            for (int nt = 0; nt < 4; nt++)
#pragma unroll
                for (int r = 0; r < 4; r++) a2[mt][nt][r] = 0.f;

#pragma unroll
        for (int ks = 0; ks < 8; ks++) {
            const int kb = ks * 16;
            uint32_t ah[2][4], al[2][4];
#pragma unroll
            for (int mt = 0; mt < 2; mt++) {
                uint32_t a_addr = sb + 2 * (OFF_HH + (warpM * 32 + mt * 16 + aRowSel) * PH + kb + aColSel);
                ldsm4(ah[mt], a_addr);
                ldsm4(al[mt], a_addr + 2 * (OFF_HL - OFF_HH));
            }
#pragma unroll
            for (int p = 0; p < 2; p++) {
                uint32_t b_addr = sb + 2 * (OFF_W2H + (warpN * 32 + p * 16 + bRowSel) * PH + kb + bColSel);
                uint32_t bh[4], bl[4];
                ldsm4(bh, b_addr);
                ldsm4(bl, b_addr + 2 * (OFF_W2L - OFF_W2H));
#pragma unroll
                for (int mt = 0; mt < 2; mt++) {
                    mma_bf16(a2[mt][2 * p],     ah[mt], bh);
                    mma_bf16(a2[mt][2 * p],     ah[mt], bl);
                    mma_bf16(a2[mt][2 * p],     al[mt], bh);
                    mma_bf16(a2[mt][2 * p + 1], ah[mt], bh + 2);
                    mma_bf16(a2[mt][2 * p + 1], ah[mt], bl + 2);
                    mma_bf16(a2[mt][2 * p + 1], al[mt], bh + 2);
                }
            }
        }

        // epilogue for this N-chunk -> g_qkvs
#pragma unroll
        for (int mt = 0; mt < 2; mt++) {
            int r0 = m0 + warpM * 32 + mt * 16 + (lane >> 2);
#pragma unroll
            for (int nt = 0; nt < 4; nt++) {
                int col = nc * 64 + warpN * 32 + nt * 8 + 2 * (lane & 3);
                float b0 = g_b2[col], b1 = g_b2[col + 1];
                if (r0 < NN) {
                    float2 o = {a2[mt][nt][0] + b0, a2[mt][nt][1] + b1};
                    *(float2*)(g_qkvs + (size_t)r0 * 512 + col) = o;
                }
                if (r0 + 8 < NN) {
                    float2 o = {a2[mt][nt][2] + b0, a2[mt][nt][3] + b1};
                    *(float2*)(g_qkvs + (size_t)(r0 + 8) * 512 + col) = o;
                }
            }
        }
        __syncthreads();
    }
}

// ---------------- W2 pack + convert (fp32 -> bf16 hi/lo) -----------------------
__global__ void conv_w2_kernel(const float* __restrict__ wq, const float* __restrict__ bq,
                               const float* __restrict__ wk, const float* __restrict__ bk,
                               const float* __restrict__ wv, const float* __restrict__ bv,
                               const float* __restrict__ ws, const float* __restrict__ bs)
{
    int i = blockIdx.x * blockDim.x + threadIdx.x;
    if (i < 512 * DH / 2) {
        int row = (2 * i) / DH;
        int kp  = i % (DH / 2);
        const float* w = (row < 128) ? wq : (row < 256) ? wk : (row < 384) ? wv : ws;
        const float2 v = ((const float2*)(w + (row & 127) * DH))[kp];
        ((uint32_t*)g_w2_hi)[i] = pack_hi2(v.x, v.y);
        ((uint32_t*)g_w2_lo)[i] = pack_lo2(v.x, v.y);
    }
    if (i < 512) {
        const float* b = (i < 128) ? bq : (i < 256) ? bk : (i < 384) ? bv : bs;
        g_b2[i] = b[i & 127];
    }
}

// ---------------- edge dtype detection ----------------------------------------
__global__ void detect_dtype_kernel(const int* __restrict__ ei_raw)
{
    __shared__ int nz;
    if (threadIdx.x == 0) nz = 0;
    __syncthreads();
    int w = ei_raw[2 * threadIdx.x + 1];
    if (w != 0) atomicAdd(&nz, 1);
    __syncthreads();
    if (threadIdx.x == 0) g_is64 = (nz == 0) ? 1 : 0;
}

// ---------------- CSR build ----------------------------------------------------
__device__ __forceinline__ int load_edge(const int* ei_raw, int e, int half)
{
    if (g_is64) return ei_raw[2 * (half * EE + e)];
    else        return ei_raw[half * EE + e];
}

__global__ void zero_deg_kernel()
{
    int i = blockIdx.x * blockDim.x + threadIdx.x;
    if (i < NN) g_deg[i] = 0;
}

__global__ void count_deg_kernel(const int* __restrict__ ei_raw)
{
    int e = blockIdx.x * blockDim.x + threadIdx.x;
    if (e < EE) {
        int dst = load_edge(ei_raw, e, 1);
        if (dst >= 0 && dst < NN) atomicAdd(&g_deg[dst], 1);
    }
}

#define SCAN_BLKS ((NN + 255) / 256)
__global__ void scan1_kernel()
{
    __shared__ int sm[256];
    int i = blockIdx.x * 256 + threadIdx.x;
    sm[threadIdx.x] = (i < NN) ? g_deg[i] : 0;
    __syncthreads();
    for (int o = 128; o > 0; o >>= 1) {
        if (threadIdx.x < o) sm[threadIdx.x] += sm[threadIdx.x + o];
        __syncthreads();
    }
    if (threadIdx.x == 0) g_part[blockIdx.x] = sm[0];
}

__global__ void scan2_kernel()
{
    __shared__ int sm[256];
    int t = threadIdx.x;
    int v = (t < SCAN_BLKS) ? g_part[t] : 0;
    sm[t] = v;
    __syncthreads();
    for (int o = 1; o < 256; o <<= 1) {
        int u = (t >= o) ? sm[t - o] : 0;
        __syncthreads();
        sm[t] += u;
        __syncthreads();
    }
    if (t < SCAN_BLKS) g_part[t] = sm[t] - v;
    if (t == 255) g_off[NN] = sm[255];
}

__global__ void scan3_kernel()
{
    __shared__ int sm[256];
    int i = blockIdx.x * 256 + threadIdx.x;
    int v = (i < NN) ? g_deg[i] : 0;
    sm[threadIdx.x] = v;
    __syncthreads();
    for (int o = 1; o < 256; o <<= 1) {
        int u = (threadIdx.x >= o) ? sm[threadIdx.x - o] : 0;
        __syncthreads();
        sm[threadIdx.x] += u;
        __syncthreads();
    }
    if (i < NN) {
        int off = g_part[blockIdx.x] + sm[threadIdx.x] - v;
        g_off[i] = off;
        g_cur[i] = off;
    }
}

__global__ void scatter_kernel(const int* __restrict__ ei_raw)
{
    int e = blockIdx.x * blockDim.x + threadIdx.x;
    if (e < EE) {
        int src = load_edge(ei_raw, e, 0);
        int dst = load_edge(ei_raw, e, 1);
        if (src >= 0 && src < NN && dst >= 0 && dst < NN) {
            int pos = atomicAdd(&g_cur[dst], 1);
            if (pos >= 0 && pos < EE) g_src[pos] = src;
        }
    }
}

// ---------------- per-node online-softmax aggregation: one warp per node -------
// Depth-2 software pipeline over the edge list.
__global__ void agg_kernel(float* __restrict__ out)
{
    int warp = (blockIdx.x * blockDim.x + threadIdx.x) >> 5;
    int lane = threadIdx.x & 31;
    if (warp >= NN) return;

    const float* myq = g_qkvs + (size_t)warp * 512;
    const float4 q = *(const float4*)(myq + 4 * lane);

    const int s = g_off[warp];
    const int e = g_off[warp + 1];

    const float scale = 0.088388347648318447f;  // 1/sqrt(128)
    float m = -INFINITY, l = 0.f;
    float4 acc = make_float4(0.f, 0.f, 0.f, 0.f);

    if (e > s) {
        float4 kk0, vv0, kk1, vv1;
        {
            const float* b0 = g_qkvs + (size_t)g_src[s] * 512;
            kk0 = *(const float4*)(b0 + 128 + 4 * lane);
            vv0 = *(const float4*)(b0 + 256 + 4 * lane);
        }
        if (s + 1 < e) {
            const float* b1 = g_qkvs + (size_t)g_src[s + 1] * 512;
            kk1 = *(const float4*)(b1 + 128 + 4 * lane);
            vv1 = *(const float4*)(b1 + 256 + 4 * lane);
        }

        for (int j = s; j < e; j++) {
            float4 kk2, vv2;
            if (j + 2 < e) {
                const float* b2 = g_qkvs + (size_t)g_src[j + 2] * 512;
                kk2 = *(const float4*)(b2 + 128 + 4 * lane);
                vv2 = *(const float4*)(b2 + 256 + 4 * lane);
            }

            float d = q.x * kk0.x + q.y * kk0.y + q.z * kk0.z + q.w * kk0.w;
            d += __shfl_xor_sync(0xffffffffu, d, 16);
            d += __shfl_xor_sync(0xffffffffu, d, 8);
            d += __shfl_xor_sync(0xffffffffu, d, 4);
            d += __shfl_xor_sync(0xffffffffu, d, 2);
            d += __shfl_xor_sync(0xffffffffu, d, 1);
            d *= scale;

            float newm = fmaxf(m, d);
            float fac = __expf(m - newm);
            float p   = __expf(d - newm);
            l = l * fac + p;

            acc.x = acc.x * fac + p * vv0.x;
            acc.y = acc.y * fac + p * vv0.y;
            acc.z = acc.z * fac + p * vv0.z;
            acc.w = acc.w * fac + p * vv0.w;
            m = newm;

            kk0 = kk1; vv0 = vv1;
            kk1 = kk2; vv1 = vv2;
        }
    }

    const float4 sk = *(const float4*)(myq + 384 + 4 * lane);
    float inv = (e > s) ? (1.f / l) : 0.f;
    float4 o;
    o.x = acc.x * inv + sk.x;
    o.y = acc.y * inv + sk.y;
    o.z = acc.z * inv + sk.z;
    o.w = acc.w * inv + sk.w;
    *(float4*)(out + (size_t)warp * DOUT + 4 * lane) = o;
}

// ---------------- launch --------------------------------------------------------
extern "C" void kernel_launch(void* const* d_in, const int* in_sizes, int n_in,
                              void* d_out, int out_size)
{
    const float* x    = (const float*)d_in[0];
    const int*   ei   = (const int*)d_in[1];
    const float* W_fc = (const float*)d_in[2];
    const float* b_fc = (const float*)d_in[3];
    const float* W_q  = (const float*)d_in[4];
    const float* b_q  = (const float*)d_in[5];
    const float* W_k  = (const float*)d_in[6];
    const float* b_k  = (const float*)d_in[7];
    const float* W_v  = (const float*)d_in[8];
    const float* b_v  = (const float*)d_in[9];
    const float* W_s  = (const float*)d_in[10];
    const float* b_s  = (const float*)d_in[11];
    float* out = (float*)d_out;

    static cudaStream_t s_side = nullptr;
    static cudaEvent_t ev_fork = nullptr, ev_join = nullptr;
    if (!s_side) {
        cudaStreamCreateWithFlags(&s_side, cudaStreamNonBlocking);
        cudaEventCreateWithFlags(&ev_fork, cudaEventDisableTiming);
        cudaEventCreateWithFlags(&ev_join, cudaEventDisableTiming);
        cudaFuncSetAttribute(fused_kernel, cudaFuncAttributeMaxDynamicSharedMemorySize,
                             SMEM_ELEMS * 2);
    }

    detect_dtype_kernel<<<1, 256>>>(ei);
    cudaEventRecord(ev_fork, 0);
    cudaStreamWaitEvent(s_side, ev_fork, 0);

    // --- side stream: CSR build ---
    zero_deg_kernel<<<(NN + 255) / 256, 256, 0, s_side>>>();
    count_deg_kernel<<<(EE + 255) / 256, 256, 0, s_side>>>(ei);
    scan1_kernel<<<SCAN_BLKS, 256, 0, s_side>>>();
    scan2_kernel<<<1, 256, 0, s_side>>>();
    scan3_kernel<<<SCAN_BLKS, 256, 0, s_side>>>();
    scatter_kernel<<<(EE + 255) / 256, 256, 0, s_side>>>(ei);
    cudaEventRecord(ev_join, s_side);

    // --- main stream: W2 conversion + fused GEMM ---
    conv_w2_kernel<<<(512 * DH / 2 + 255) / 256, 256>>>(W_q, b_q, W_k, b_k, W_v, b_v, W_s, b_s);
    fused_kernel<<<(NN + 127) / 128, 256, SMEM_ELEMS * 2>>>(x, W_fc, b_fc);

    // join, then aggregate
    cudaStreamWaitEvent(0, ev_join, 0);
    agg_kernel<<<(NN * 32 + 255) / 256, 256>>>(out);
}

// round 12
// speedup vs baseline: 1.1511x; 1.0114x over previous
#include <cuda_runtime.h>
#include <cuda_bf16.h>
#include <math.h>
#include <stdint.h>

#define NN 50000
#define EE 800000
#define DIN 256
#define DH 128
#define DOUT 128

// ---------------- scratch (device globals; no allocation allowed) -------------
__device__ __nv_bfloat16 g_w2_hi[512 * DH];
__device__ __nv_bfloat16 g_w2_lo[512 * DH];
__device__ float g_b2[512];
__device__ float g_qkvs[(size_t)NN * 512];          // 102.4 MB : per node [q k v skip]
__device__ int   g_deg[NN];
__device__ int   g_off[NN + 1];
__device__ int   g_cur[NN];
__device__ int   g_src[EE];
__device__ int   g_part[256];
__device__ int   g_is64;

// ---------------- helpers ------------------------------------------------------
__device__ __forceinline__ uint32_t smem_u32(const void* p) {
    uint32_t a;
    asm("{ .reg .u64 t; cvta.to.shared.u64 t, %1; cvt.u32.u64 %0, t; }" : "=r"(a) : "l"(p));
    return a;
}
__device__ __forceinline__ uint32_t pack_hi2(float a, float b) {
    __nv_bfloat162 t = __floats2bfloat162_rn(a, b);
    return *(uint32_t*)&t;
}
__device__ __forceinline__ uint32_t pack_lo2(float a, float b) {
    float ra = a - __bfloat162float(__float2bfloat16_rn(a));
    float rb = b - __bfloat162float(__float2bfloat16_rn(b));
    __nv_bfloat162 t = __floats2bfloat162_rn(ra, rb);
    return *(uint32_t*)&t;
}
__device__ __forceinline__ void mma_bf16(float d[4], const uint32_t a[4], const uint32_t b[2]) {
    asm volatile(
        "mma.sync.aligned.m16n8k16.row.col.f32.bf16.bf16.f32 "
        "{%0,%1,%2,%3}, {%4,%5,%6,%7}, {%8,%9}, {%0,%1,%2,%3};"
        : "+f"(d[0]), "+f"(d[1]), "+f"(d[2]), "+f"(d[3])
        : "r"(a[0]), "r"(a[1]), "r"(a[2]), "r"(a[3]), "r"(b[0]), "r"(b[1]));
}
__device__ __forceinline__ void ldsm4(uint32_t r[4], uint32_t addr) {
    asm volatile("ldmatrix.sync.aligned.m8n8.x4.shared.b16 {%0,%1,%2,%3}, [%4];"
                 : "=r"(r[0]), "=r"(r[1]), "=r"(r[2]), "=r"(r[3]) : "r"(addr));
}

// ---------------- fused GEMM: x -> h (SMEM) -> qkvs -----------------------------
#define PAD1 40
#define PH   136
#define OFF_ASH 0
#define OFF_ASL 5120
#define OFF_BSH 10240
#define OFF_BSL 15360
#define OFF_HH  20480
#define OFF_HL  37888
#define OFF_W2H 0
#define OFF_W2L 8704
#define SMEM_ELEMS 55296   // 110592 bytes

__global__ __launch_bounds__(256) void fused_kernel(const float* __restrict__ x,
                                                    const float* __restrict__ w1,
                                                    const float* __restrict__ bias1)
{
    extern __shared__ __nv_bfloat16 sm[];
    const int tid = threadIdx.x, lane = tid & 31, wid = tid >> 5;
    const int warpM = wid & 3, warpN = wid >> 2;
    const int m0 = blockIdx.x * 128;
    const uint32_t sb = smem_u32(sm);

    const int aRowSel = lane & 15;
    const int aColSel = (lane >> 4) << 3;
    const int bRowSel = ((lane >> 4) << 3) + (lane & 7);
    const int bColSel = ((lane >> 3) & 1) << 3;

    // ---------------- phase 1: K=256 mainloop -----------------------------------
    float acc[2][8][4];
#pragma unroll
    for (int mt = 0; mt < 2; mt++)
#pragma unroll
        for (int nt = 0; nt < 8; nt++)
#pragma unroll
            for (int r = 0; r < 4; r++) acc[mt][nt][r] = 0.f;

    float4 rA[4], rB[4];
    const int arow = tid >> 3, ac4 = tid & 7;
#pragma unroll
    for (int it = 0; it < 4; it++) {
        int row = arow + it * 32;
        int grow = m0 + row;
        rA[it] = (grow < NN) ? *(const float4*)(x + (size_t)grow * DIN + ac4 * 4)
                             : make_float4(0.f, 0.f, 0.f, 0.f);
        rB[it] = *(const float4*)(w1 + (size_t)row * DIN + ac4 * 4);
    }

    for (int k0 = 0; k0 < DIN; k0 += 32) {
#pragma unroll
        for (int it = 0; it < 4; it++) {
            int row = arow + it * 32;
            float4 v = rA[it];
            *(uint2*)(sm + OFF_ASH + row * PAD1 + ac4 * 4) = make_uint2(pack_hi2(v.x, v.y), pack_hi2(v.z, v.w));
            *(uint2*)(sm + OFF_ASL + row * PAD1 + ac4 * 4) = make_uint2(pack_lo2(v.x, v.y), pack_lo2(v.z, v.w));
            v = rB[it];
            *(uint2*)(sm + OFF_BSH + row * PAD1 + ac4 * 4) = make_uint2(pack_hi2(v.x, v.y), pack_hi2(v.z, v.w));
            *(uint2*)(sm + OFF_BSL + row * PAD1 + ac4 * 4) = make_uint2(pack_lo2(v.x, v.y), pack_lo2(v.z, v.w));
        }
        __syncthreads();

        if (k0 + 32 < DIN) {
#pragma unroll
            for (int it = 0; it < 4; it++) {
                int row = arow + it * 32;
                int grow = m0 + row;
                rA[it] = (grow < NN) ? *(const float4*)(x + (size_t)grow * DIN + k0 + 32 + ac4 * 4)
                                     : make_float4(0.f, 0.f, 0.f, 0.f);
                rB[it] = *(const float4*)(w1 + (size_t)row * DIN + k0 + 32 + ac4 * 4);
            }
        }

#pragma unroll
        for (int ks = 0; ks < 2; ks++) {
            const int kb = ks * 16;
            uint32_t ah[2][4], al[2][4];
#pragma unroll
            for (int mt = 0; mt < 2; mt++) {
                uint32_t a_addr = sb + 2 * (OFF_ASH + (warpM * 32 + mt * 16 + aRowSel) * PAD1 + kb + aColSel);
                ldsm4(ah[mt], a_addr);
                ldsm4(al[mt], a_addr + 2 * (OFF_ASL - OFF_ASH));
            }
#pragma unroll
            for (int p = 0; p < 4; p++) {
                uint32_t b_addr = sb + 2 * (OFF_BSH + (warpN * 64 + p * 16 + bRowSel) * PAD1 + kb + bColSel);
                uint32_t bh[4], bl[4];
                ldsm4(bh, b_addr);
                ldsm4(bl, b_addr + 2 * (OFF_BSL - OFF_BSH));
#pragma unroll
                for (int mt = 0; mt < 2; mt++) {
                    mma_bf16(acc[mt][2 * p],     ah[mt], bh);
                    mma_bf16(acc[mt][2 * p],     ah[mt], bl);
                    mma_bf16(acc[mt][2 * p],     al[mt], bh);
                    mma_bf16(acc[mt][2 * p + 1], ah[mt], bh + 2);
                    mma_bf16(acc[mt][2 * p + 1], ah[mt], bl + 2);
                    mma_bf16(acc[mt][2 * p + 1], al[mt], bh + 2);
                }
            }
        }
        __syncthreads();
    }

    // prefetch W2 chunk 0 (overlaps h epilogue)
    uint4 rWh[4], rWl[4];
    const int brow = tid >> 4, bchunk = tid & 15;
#pragma unroll
    for (int it = 0; it < 4; it++) {
        int row = brow + it * 16;
        rWh[it] = *(const uint4*)(g_w2_hi + (size_t)row * DH + bchunk * 8);
        rWl[it] = *(const uint4*)(g_w2_lo + (size_t)row * DH + bchunk * 8);
    }

    // h epilogue: bias + relu -> SMEM (bf16 hi/lo)
#pragma unroll
    for (int mt = 0; mt < 2; mt++) {
        int r0 = warpM * 32 + mt * 16 + (lane >> 2);
#pragma unroll
        for (int nt = 0; nt < 8; nt++) {
            int col = warpN * 64 + nt * 8 + 2 * (lane & 3);
            float b0 = bias1[col], b1 = bias1[col + 1];
            float v0 = fmaxf(acc[mt][nt][0] + b0, 0.f);
            float v1 = fmaxf(acc[mt][nt][1] + b1, 0.f);
            float v2 = fmaxf(acc[mt][nt][2] + b0, 0.f);
            float v3 = fmaxf(acc[mt][nt][3] + b1, 0.f);
            *(uint32_t*)(sm + OFF_HH + r0 * PH + col) = pack_hi2(v0, v1);
            *(uint32_t*)(sm + OFF_HL + r0 * PH + col) = pack_lo2(v0, v1);
            *(uint32_t*)(sm + OFF_HH + (r0 + 8) * PH + col) = pack_hi2(v2, v3);
            *(uint32_t*)(sm + OFF_HL + (r0 + 8) * PH + col) = pack_lo2(v2, v3);
        }
    }
    __syncthreads();

    // ---------------- phase 2: qkvs = h @ W2^T + b2 ------------------------------
    for (int nc = 0; nc < 8; nc++) {
#pragma unroll
        for (int it = 0; it < 4; it++) {
            int row = brow + it * 16;
            *(uint4*)(sm + OFF_W2H + row * PH + bchunk * 8) = rWh[it];
            *(uint4*)(sm + OFF_W2L + row * PH + bchunk * 8) = rWl[it];
        }
        __syncthreads();

        if (nc + 1 < 8) {
#pragma unroll
            for (int it = 0; it < 4; it++) {
                int row = (nc + 1) * 64 + brow + it * 16;
                rWh[it] = *(const uint4*)(g_w2_hi + (size_t)row * DH + bchunk * 8);
                rWl[it] = *(const uint4*)(g_w2_lo + (size_t)row * DH + bchunk * 8);
            }
        }

        float a2[2][4][4];
#pragma unroll
        for (int mt = 0; mt < 2; mt++)
#pragma unroll
            for (int nt = 0; nt < 4; nt++)
#pragma unroll
                for (int r = 0; r < 4; r++) a2[mt][nt][r] = 0.f;

#pragma unroll
        for (int ks = 0; ks < 8; ks++) {
            const int kb = ks * 16;
            uint32_t ah[2][4], al[2][4];
#pragma unroll
            for (int mt = 0; mt < 2; mt++) {
                uint32_t a_addr = sb + 2 * (OFF_HH + (warpM * 32 + mt * 16 + aRowSel) * PH + kb + aColSel);
                ldsm4(ah[mt], a_addr);
                ldsm4(al[mt], a_addr + 2 * (OFF_HL - OFF_HH));
            }
#pragma unroll
            for (int p = 0; p < 2; p++) {
                uint32_t b_addr = sb + 2 * (OFF_W2H + (warpN * 32 + p * 16 + bRowSel) * PH + kb + bColSel);
                uint32_t bh[4], bl[4];
                ldsm4(bh, b_addr);
                ldsm4(bl, b_addr + 2 * (OFF_W2L - OFF_W2H));
#pragma unroll
                for (int mt = 0; mt < 2; mt++) {
                    mma_bf16(a2[mt][2 * p],     ah[mt], bh);
                    mma_bf16(a2[mt][2 * p],     ah[mt], bl);
                    mma_bf16(a2[mt][2 * p],     al[mt], bh);
                    mma_bf16(a2[mt][2 * p + 1], ah[mt], bh + 2);
                    mma_bf16(a2[mt][2 * p + 1], ah[mt], bl + 2);
                    mma_bf16(a2[mt][2 * p + 1], al[mt], bh + 2);
                }
            }
        }

        // epilogue for this N-chunk -> g_qkvs
#pragma unroll
        for (int mt = 0; mt < 2; mt++) {
            int r0 = m0 + warpM * 32 + mt * 16 + (lane >> 2);
#pragma unroll
            for (int nt = 0; nt < 4; nt++) {
                int col = nc * 64 + warpN * 32 + nt * 8 + 2 * (lane & 3);
                float b0 = g_b2[col], b1 = g_b2[col + 1];
                if (r0 < NN) {
                    float2 o = {a2[mt][nt][0] + b0, a2[mt][nt][1] + b1};
                    *(float2*)(g_qkvs + (size_t)r0 * 512 + col) = o;
                }
                if (r0 + 8 < NN) {
                    float2 o = {a2[mt][nt][2] + b0, a2[mt][nt][3] + b1};
                    *(float2*)(g_qkvs + (size_t)(r0 + 8) * 512 + col) = o;
                }
            }
        }
        __syncthreads();
    }
}

// ---------------- W2 pack + convert (fp32 -> bf16 hi/lo) -----------------------
__global__ void conv_w2_kernel(const float* __restrict__ wq, const float* __restrict__ bq,
                               const float* __restrict__ wk, const float* __restrict__ bk,
                               const float* __restrict__ wv, const float* __restrict__ bv,
                               const float* __restrict__ ws, const float* __restrict__ bs)
{
    int i = blockIdx.x * blockDim.x + threadIdx.x;
    if (i < 512 * DH / 2) {
        int row = (2 * i) / DH;
        int kp  = i % (DH / 2);
        const float* w = (row < 128) ? wq : (row < 256) ? wk : (row < 384) ? wv : ws;
        const float2 v = ((const float2*)(w + (row & 127) * DH))[kp];
        ((uint32_t*)g_w2_hi)[i] = pack_hi2(v.x, v.y);
        ((uint32_t*)g_w2_lo)[i] = pack_lo2(v.x, v.y);
    }
    if (i < 512) {
        const float* b = (i < 128) ? bq : (i < 256) ? bk : (i < 384) ? bv : bs;
        g_b2[i] = b[i & 127];
    }
}

// ---------------- edge dtype detection ----------------------------------------
__global__ void detect_dtype_kernel(const int* __restrict__ ei_raw)
{
    __shared__ int nz;
    if (threadIdx.x == 0) nz = 0;
    __syncthreads();
    int w = ei_raw[2 * threadIdx.x + 1];
    if (w != 0) atomicAdd(&nz, 1);
    __syncthreads();
    if (threadIdx.x == 0) g_is64 = (nz == 0) ? 1 : 0;
}

// ---------------- CSR build ----------------------------------------------------
__device__ __forceinline__ int load_edge(const int* ei_raw, int e, int half)
{
    if (g_is64) return ei_raw[2 * (half * EE + e)];
    else        return ei_raw[half * EE + e];
}

__global__ void zero_deg_kernel()
{
    int i = blockIdx.x * blockDim.x + threadIdx.x;
    if (i < NN) g_deg[i] = 0;
}

__global__ void count_deg_kernel(const int* __restrict__ ei_raw)
{
    int e = blockIdx.x * blockDim.x + threadIdx.x;
    if (e < EE) {
        int dst = load_edge(ei_raw, e, 1);
        if (dst >= 0 && dst < NN) atomicAdd(&g_deg[dst], 1);
    }
}

#define SCAN_BLKS ((NN + 255) / 256)
__global__ void scan1_kernel()
{
    __shared__ int sm[256];
    int i = blockIdx.x * 256 + threadIdx.x;
    sm[threadIdx.x] = (i < NN) ? g_deg[i] : 0;
    __syncthreads();
    for (int o = 128; o > 0; o >>= 1) {
        if (threadIdx.x < o) sm[threadIdx.x] += sm[threadIdx.x + o];
        __syncthreads();
    }
    if (threadIdx.x == 0) g_part[blockIdx.x] = sm[0];
}

__global__ void scan2_kernel()
{
    __shared__ int sm[256];
    int t = threadIdx.x;
    int v = (t < SCAN_BLKS) ? g_part[t] : 0;
    sm[t] = v;
    __syncthreads();
    for (int o = 1; o < 256; o <<= 1) {
        int u = (t >= o) ? sm[t - o] : 0;
        __syncthreads();
        sm[t] += u;
        __syncthreads();
    }
    if (t < SCAN_BLKS) g_part[t] = sm[t] - v;
    if (t == 255) g_off[NN] = sm[255];
}

__global__ void scan3_kernel()
{
    __shared__ int sm[256];
    int i = blockIdx.x * 256 + threadIdx.x;
    int v = (i < NN) ? g_deg[i] : 0;
    sm[threadIdx.x] = v;
    __syncthreads();
    for (int o = 1; o < 256; o <<= 1) {
        int u = (threadIdx.x >= o) ? sm[threadIdx.x - o] : 0;
        __syncthreads();
        sm[threadIdx.x] += u;
        __syncthreads();
    }
    if (i < NN) {
        int off = g_part[blockIdx.x] + sm[threadIdx.x] - v;
        g_off[i] = off;
        g_cur[i] = off;
    }
}

__global__ void scatter_kernel(const int* __restrict__ ei_raw)
{
    int e = blockIdx.x * blockDim.x + threadIdx.x;
    if (e < EE) {
        int src = load_edge(ei_raw, e, 0);
        int dst = load_edge(ei_raw, e, 1);
        if (src >= 0 && src < NN && dst >= 0 && dst < NN) {
            int pos = atomicAdd(&g_cur[dst], 1);
            if (pos >= 0 && pos < EE) g_src[pos] = src;
        }
    }
}

// ---------------- per-node online-softmax aggregation: one warp per node -------
// Depth-1 software pipeline (R8 configuration — measured best).
__global__ void agg_kernel(float* __restrict__ out)
{
    int warp = (blockIdx.x * blockDim.x + threadIdx.x) >> 5;
    int lane = threadIdx.x & 31;
    if (warp >= NN) return;

    const float* myq = g_qkvs + (size_t)warp * 512;
    const float4 q = *(const float4*)(myq + 4 * lane);

    const int s = g_off[warp];
    const int e = g_off[warp + 1];

    const float scale = 0.088388347648318447f;  // 1/sqrt(128)
    float m = -INFINITY, l = 0.f;
    float4 acc = make_float4(0.f, 0.f, 0.f, 0.f);

    if (e > s) {
        int src = g_src[s];
        const float* base = g_qkvs + (size_t)src * 512;
        float4 kk = *(const float4*)(base + 128 + 4 * lane);
        float4 vv = *(const float4*)(base + 256 + 4 * lane);

        for (int j = s; j < e; j++) {
            float4 kk_n, vv_n;
            if (j + 1 < e) {
                int src_n = g_src[j + 1];
                const float* base_n = g_qkvs + (size_t)src_n * 512;
                kk_n = *(const float4*)(base_n + 128 + 4 * lane);
                vv_n = *(const float4*)(base_n + 256 + 4 * lane);
            }

            float d = q.x * kk.x + q.y * kk.y + q.z * kk.z + q.w * kk.w;
            d += __shfl_xor_sync(0xffffffffu, d, 16);
            d += __shfl_xor_sync(0xffffffffu, d, 8);
            d += __shfl_xor_sync(0xffffffffu, d, 4);
            d += __shfl_xor_sync(0xffffffffu, d, 2);
            d += __shfl_xor_sync(0xffffffffu, d, 1);
            d *= scale;

            float newm = fmaxf(m, d);
            float fac = __expf(m - newm);
            float p   = __expf(d - newm);
            l = l * fac + p;

            acc.x = acc.x * fac + p * vv.x;
            acc.y = acc.y * fac + p * vv.y;
            acc.z = acc.z * fac + p * vv.z;
            acc.w = acc.w * fac + p * vv.w;
            m = newm;

            kk = kk_n;
            vv = vv_n;
        }
    }

    const float4 sk = *(const float4*)(myq + 384 + 4 * lane);
    float inv = (e > s) ? (1.f / l) : 0.f;
    float4 o;
    o.x = acc.x * inv + sk.x;
    o.y = acc.y * inv + sk.y;
    o.z = acc.z * inv + sk.z;
    o.w = acc.w * inv + sk.w;
    *(float4*)(out + (size_t)warp * DOUT + 4 * lane) = o;
}

// ---------------- launch --------------------------------------------------------
extern "C" void kernel_launch(void* const* d_in, const int* in_sizes, int n_in,
                              void* d_out, int out_size)
{
    const float* x    = (const float*)d_in[0];
    const int*   ei   = (const int*)d_in[1];
    const float* W_fc = (const float*)d_in[2];
    const float* b_fc = (const float*)d_in[3];
    const float* W_q  = (const float*)d_in[4];
    const float* b_q  = (const float*)d_in[5];
    const float* W_k  = (const float*)d_in[6];
    const float* b_k  = (const float*)d_in[7];
    const float* W_v  = (const float*)d_in[8];
    const float* b_v  = (const float*)d_in[9];
    const float* W_s  = (const float*)d_in[10];
    const float* b_s  = (const float*)d_in[11];
    float* out = (float*)d_out;

    static cudaStream_t s_side = nullptr;
    static cudaEvent_t ev_fork = nullptr, ev_join = nullptr;
    if (!s_side) {
        cudaStreamCreateWithFlags(&s_side, cudaStreamNonBlocking);
        cudaEventCreateWithFlags(&ev_fork, cudaEventDisableTiming);
        cudaEventCreateWithFlags(&ev_join, cudaEventDisableTiming);
        cudaFuncSetAttribute(fused_kernel, cudaFuncAttributeMaxDynamicSharedMemorySize,
                             SMEM_ELEMS * 2);
    }

    // fork side stream immediately; detect + CSR chain live entirely there
    cudaEventRecord(ev_fork, 0);
    cudaStreamWaitEvent(s_side, ev_fork, 0);

    // --- side stream: dtype detection + CSR build ---
    detect_dtype_kernel<<<1, 256, 0, s_side>>>(ei);
    zero_deg_kernel<<<(NN + 255) / 256, 256, 0, s_side>>>();
    count_deg_kernel<<<(EE + 255) / 256, 256, 0, s_side>>>(ei);
    scan1_kernel<<<SCAN_BLKS, 256, 0, s_side>>>();
    scan2_kernel<<<1, 256, 0, s_side>>>();
    scan3_kernel<<<SCAN_BLKS, 256, 0, s_side>>>();
    scatter_kernel<<<(EE + 255) / 256, 256, 0, s_side>>>(ei);
    cudaEventRecord(ev_join, s_side);

    // --- main stream: W2 conversion + fused GEMM ---
    conv_w2_kernel<<<(512 * DH / 2 + 255) / 256, 256>>>(W_q, b_q, W_k, b_k, W_v, b_v, W_s, b_s);
    fused_kernel<<<(NN + 127) / 128, 256, SMEM_ELEMS * 2>>>(x, W_fc, b_fc);

    // join, then aggregate
    cudaStreamWaitEvent(0, ev_join, 0);
    agg_kernel<<<(NN * 32 + 255) / 256, 256>>>(out);
}

// round 13
// speedup vs baseline: 1.1767x; 1.0223x over previous
#include <cuda_runtime.h>
#include <cuda_bf16.h>
#include <math.h>
#include <stdint.h>

#define NN 50000
#define EE 800000
#define DIN 256
#define DH 128
#define DOUT 128

// ---------------- scratch (device globals; no allocation allowed) -------------
__device__ __nv_bfloat16 g_w2_hi[512 * DH];
__device__ __nv_bfloat16 g_w2_lo[512 * DH];
__device__ float g_b2[512];
__device__ float g_qkvs[(size_t)NN * 512];          // 102.4 MB : per node [q k v skip]
__device__ int   g_deg[NN];
__device__ int   g_off[NN + 1];
__device__ int   g_cur[NN];
__device__ int   g_src[EE];
__device__ int   g_part[256];
__device__ int   g_is64;

// ---------------- helpers ------------------------------------------------------
__device__ __forceinline__ uint32_t smem_u32(const void* p) {
    uint32_t a;
    asm("{ .reg .u64 t; cvta.to.shared.u64 t, %1; cvt.u32.u64 %0, t; }" : "=r"(a) : "l"(p));
    return a;
}
__device__ __forceinline__ uint32_t pack_hi2(float a, float b) {
    __nv_bfloat162 t = __floats2bfloat162_rn(a, b);
    return *(uint32_t*)&t;
}
__device__ __forceinline__ uint32_t pack_lo2(float a, float b) {
    float ra = a - __bfloat162float(__float2bfloat16_rn(a));
    float rb = b - __bfloat162float(__float2bfloat16_rn(b));
    __nv_bfloat162 t = __floats2bfloat162_rn(ra, rb);
    return *(uint32_t*)&t;
}
__device__ __forceinline__ void mma_bf16(float d[4], const uint32_t a[4], const uint32_t b[2]) {
    asm volatile(
        "mma.sync.aligned.m16n8k16.row.col.f32.bf16.bf16.f32 "
        "{%0,%1,%2,%3}, {%4,%5,%6,%7}, {%8,%9}, {%0,%1,%2,%3};"
        : "+f"(d[0]), "+f"(d[1]), "+f"(d[2]), "+f"(d[3])
        : "r"(a[0]), "r"(a[1]), "r"(a[2]), "r"(a[3]), "r"(b[0]), "r"(b[1]));
}
__device__ __forceinline__ void ldsm4(uint32_t r[4], uint32_t addr) {
    asm volatile("ldmatrix.sync.aligned.m8n8.x4.shared.b16 {%0,%1,%2,%3}, [%4];"
                 : "=r"(r[0]), "=r"(r[1]), "=r"(r[2]), "=r"(r[3]) : "r"(addr));
}

// ---------------- fused GEMM: x -> h (SMEM) -> qkvs -----------------------------
#define PAD1 40
#define PH   136
#define OFF_ASH 0
#define OFF_ASL 5120
#define OFF_BSH 10240
#define OFF_BSL 15360
#define OFF_HH  20480
#define OFF_HL  37888
#define OFF_W2H 0
#define OFF_W2L 8704
#define SMEM_ELEMS 55296   // 110592 bytes

__global__ __launch_bounds__(256) void fused_kernel(const float* __restrict__ x,
                                                    const float* __restrict__ w1,
                                                    const float* __restrict__ bias1)
{
    extern __shared__ __nv_bfloat16 sm[];
    const int tid = threadIdx.x, lane = tid & 31, wid = tid >> 5;
    const int warpM = wid & 3, warpN = wid >> 2;
    const int m0 = blockIdx.x * 128;
    const uint32_t sb = smem_u32(sm);

    const int aRowSel = lane & 15;
    const int aColSel = (lane >> 4) << 3;
    const int bRowSel = ((lane >> 4) << 3) + (lane & 7);
    const int bColSel = ((lane >> 3) & 1) << 3;

    // ---------------- phase 1: K=256 mainloop -----------------------------------
    float acc[2][8][4];
#pragma unroll
    for (int mt = 0; mt < 2; mt++)
#pragma unroll
        for (int nt = 0; nt < 8; nt++)
#pragma unroll
            for (int r = 0; r < 4; r++) acc[mt][nt][r] = 0.f;

    float4 rA[4], rB[4];
    const int arow = tid >> 3, ac4 = tid & 7;
#pragma unroll
    for (int it = 0; it < 4; it++) {
        int row = arow + it * 32;
        int grow = m0 + row;
        rA[it] = (grow < NN) ? *(const float4*)(x + (size_t)grow * DIN + ac4 * 4)
                             : make_float4(0.f, 0.f, 0.f, 0.f);
        rB[it] = *(const float4*)(w1 + (size_t)row * DIN + ac4 * 4);
    }

    for (int k0 = 0; k0 < DIN; k0 += 32) {
#pragma unroll
        for (int it = 0; it < 4; it++) {
            int row = arow + it * 32;
            float4 v = rA[it];
            *(uint2*)(sm + OFF_ASH + row * PAD1 + ac4 * 4) = make_uint2(pack_hi2(v.x, v.y), pack_hi2(v.z, v.w));
            *(uint2*)(sm + OFF_ASL + row * PAD1 + ac4 * 4) = make_uint2(pack_lo2(v.x, v.y), pack_lo2(v.z, v.w));
            v = rB[it];
            *(uint2*)(sm + OFF_BSH + row * PAD1 + ac4 * 4) = make_uint2(pack_hi2(v.x, v.y), pack_hi2(v.z, v.w));
            *(uint2*)(sm + OFF_BSL + row * PAD1 + ac4 * 4) = make_uint2(pack_lo2(v.x, v.y), pack_lo2(v.z, v.w));
        }
        __syncthreads();

        if (k0 + 32 < DIN) {
#pragma unroll
            for (int it = 0; it < 4; it++) {
                int row = arow + it * 32;
                int grow = m0 + row;
                rA[it] = (grow < NN) ? *(const float4*)(x + (size_t)grow * DIN + k0 + 32 + ac4 * 4)
                                     : make_float4(0.f, 0.f, 0.f, 0.f);
                rB[it] = *(const float4*)(w1 + (size_t)row * DIN + k0 + 32 + ac4 * 4);
            }
        }

#pragma unroll
        for (int ks = 0; ks < 2; ks++) {
            const int kb = ks * 16;
            uint32_t ah[2][4], al[2][4];
#pragma unroll
            for (int mt = 0; mt < 2; mt++) {
                uint32_t a_addr = sb + 2 * (OFF_ASH + (warpM * 32 + mt * 16 + aRowSel) * PAD1 + kb + aColSel);
                ldsm4(ah[mt], a_addr);
                ldsm4(al[mt], a_addr + 2 * (OFF_ASL - OFF_ASH));
            }
#pragma unroll
            for (int p = 0; p < 4; p++) {
                uint32_t b_addr = sb + 2 * (OFF_BSH + (warpN * 64 + p * 16 + bRowSel) * PAD1 + kb + bColSel);
                uint32_t bh[4], bl[4];
                ldsm4(bh, b_addr);
                ldsm4(bl, b_addr + 2 * (OFF_BSL - OFF_BSH));
#pragma unroll
                for (int mt = 0; mt < 2; mt++) {
                    mma_bf16(acc[mt][2 * p],     ah[mt], bh);
                    mma_bf16(acc[mt][2 * p],     ah[mt], bl);
                    mma_bf16(acc[mt][2 * p],     al[mt], bh);
                    mma_bf16(acc[mt][2 * p + 1], ah[mt], bh + 2);
                    mma_bf16(acc[mt][2 * p + 1], ah[mt], bl + 2);
                    mma_bf16(acc[mt][2 * p + 1], al[mt], bh + 2);
                }
            }
        }
        __syncthreads();
    }

    // prefetch W2 chunk 0 (overlaps h epilogue)
    uint4 rWh[4], rWl[4];
    const int brow = tid >> 4, bchunk = tid & 15;
#pragma unroll
    for (int it = 0; it < 4; it++) {
        int row = brow + it * 16;
        rWh[it] = *(const uint4*)(g_w2_hi + (size_t)row * DH + bchunk * 8);
        rWl[it] = *(const uint4*)(g_w2_lo + (size_t)row * DH + bchunk * 8);
    }

    // h epilogue: bias + relu -> SMEM (bf16 hi/lo)
#pragma unroll
    for (int mt = 0; mt < 2; mt++) {
        int r0 = warpM * 32 + mt * 16 + (lane >> 2);
#pragma unroll
        for (int nt = 0; nt < 8; nt++) {
            int col = warpN * 64 + nt * 8 + 2 * (lane & 3);
            float b0 = bias1[col], b1 = bias1[col + 1];
            float v0 = fmaxf(acc[mt][nt][0] + b0, 0.f);
            float v1 = fmaxf(acc[mt][nt][1] + b1, 0.f);
            float v2 = fmaxf(acc[mt][nt][2] + b0, 0.f);
            float v3 = fmaxf(acc[mt][nt][3] + b1, 0.f);
            *(uint32_t*)(sm + OFF_HH + r0 * PH + col) = pack_hi2(v0, v1);
            *(uint32_t*)(sm + OFF_HL + r0 * PH + col) = pack_lo2(v0, v1);
            *(uint32_t*)(sm + OFF_HH + (r0 + 8) * PH + col) = pack_hi2(v2, v3);
            *(uint32_t*)(sm + OFF_HL + (r0 + 8) * PH + col) = pack_lo2(v2, v3);
        }
    }
    __syncthreads();

    // ---------------- phase 2: qkvs = h @ W2^T + b2 ------------------------------
    for (int nc = 0; nc < 8; nc++) {
#pragma unroll
        for (int it = 0; it < 4; it++) {
            int row = brow + it * 16;
            *(uint4*)(sm + OFF_W2H + row * PH + bchunk * 8) = rWh[it];
            *(uint4*)(sm + OFF_W2L + row * PH + bchunk * 8) = rWl[it];
        }
        __syncthreads();

        if (nc + 1 < 8) {
#pragma unroll
            for (int it = 0; it < 4; it++) {
                int row = (nc + 1) * 64 + brow + it * 16;
                rWh[it] = *(const uint4*)(g_w2_hi + (size_t)row * DH + bchunk * 8);
                rWl[it] = *(const uint4*)(g_w2_lo + (size_t)row * DH + bchunk * 8);
            }
        }

        float a2[2][4][4];
#pragma unroll
        for (int mt = 0; mt < 2; mt++)
#pragma unroll
            for (int nt = 0; nt < 4; nt++)
#pragma unroll
                for (int r = 0; r < 4; r++) a2[mt][nt][r] = 0.f;

#pragma unroll
        for (int ks = 0; ks < 8; ks++) {
            const int kb = ks * 16;
            uint32_t ah[2][4], al[2][4];
#pragma unroll
            for (int mt = 0; mt < 2; mt++) {
                uint32_t a_addr = sb + 2 * (OFF_HH + (warpM * 32 + mt * 16 + aRowSel) * PH + kb + aColSel);
                ldsm4(ah[mt], a_addr);
                ldsm4(al[mt], a_addr + 2 * (OFF_HL - OFF_HH));
            }
#pragma unroll
            for (int p = 0; p < 2; p++) {
                uint32_t b_addr = sb + 2 * (OFF_W2H + (warpN * 32 + p * 16 + bRowSel) * PH + kb + bColSel);
                uint32_t bh[4], bl[4];
                ldsm4(bh, b_addr);
                ldsm4(bl, b_addr + 2 * (OFF_W2L - OFF_W2H));
#pragma unroll
                for (int mt = 0; mt < 2; mt++) {
                    mma_bf16(a2[mt][2 * p],     ah[mt], bh);
                    mma_bf16(a2[mt][2 * p],     ah[mt], bl);
                    mma_bf16(a2[mt][2 * p],     al[mt], bh);
                    mma_bf16(a2[mt][2 * p + 1], ah[mt], bh + 2);
                    mma_bf16(a2[mt][2 * p + 1], ah[mt], bl + 2);
                    mma_bf16(a2[mt][2 * p + 1], al[mt], bh + 2);
                }
            }
        }

        // epilogue for this N-chunk -> g_qkvs
#pragma unroll
        for (int mt = 0; mt < 2; mt++) {
            int r0 = m0 + warpM * 32 + mt * 16 + (lane >> 2);
#pragma unroll
            for (int nt = 0; nt < 4; nt++) {
                int col = nc * 64 + warpN * 32 + nt * 8 + 2 * (lane & 3);
                float b0 = g_b2[col], b1 = g_b2[col + 1];
                if (r0 < NN) {
                    float2 o = {a2[mt][nt][0] + b0, a2[mt][nt][1] + b1};
                    *(float2*)(g_qkvs + (size_t)r0 * 512 + col) = o;
                }
                if (r0 + 8 < NN) {
                    float2 o = {a2[mt][nt][2] + b0, a2[mt][nt][3] + b1};
                    *(float2*)(g_qkvs + (size_t)(r0 + 8) * 512 + col) = o;
                }
            }
        }
        __syncthreads();
    }
}

// ---------------- W2 pack + convert (fp32 -> bf16 hi/lo) -----------------------
__global__ void conv_w2_kernel(const float* __restrict__ wq, const float* __restrict__ bq,
                               const float* __restrict__ wk, const float* __restrict__ bk,
                               const float* __restrict__ wv, const float* __restrict__ bv,
                               const float* __restrict__ ws, const float* __restrict__ bs)
{
    int i = blockIdx.x * blockDim.x + threadIdx.x;
    if (i < 512 * DH / 2) {
        int row = (2 * i) / DH;
        int kp  = i % (DH / 2);
        const float* w = (row < 128) ? wq : (row < 256) ? wk : (row < 384) ? wv : ws;
        const float2 v = ((const float2*)(w + (row & 127) * DH))[kp];
        ((uint32_t*)g_w2_hi)[i] = pack_hi2(v.x, v.y);
        ((uint32_t*)g_w2_lo)[i] = pack_lo2(v.x, v.y);
    }
    if (i < 512) {
        const float* b = (i < 128) ? bq : (i < 256) ? bk : (i < 384) ? bv : bs;
        g_b2[i] = b[i & 127];
    }
}

// ---------------- edge dtype detection ----------------------------------------
__global__ void detect_dtype_kernel(const int* __restrict__ ei_raw)
{
    __shared__ int nz;
    if (threadIdx.x == 0) nz = 0;
    __syncthreads();
    int w = ei_raw[2 * threadIdx.x + 1];
    if (w != 0) atomicAdd(&nz, 1);
    __syncthreads();
    if (threadIdx.x == 0) g_is64 = (nz == 0) ? 1 : 0;
}

// ---------------- CSR build ----------------------------------------------------
__device__ __forceinline__ int load_edge(const int* ei_raw, int e, int half)
{
    if (g_is64) return ei_raw[2 * (half * EE + e)];
    else        return ei_raw[half * EE + e];
}

__global__ void zero_deg_kernel()
{
    int i = blockIdx.x * blockDim.x + threadIdx.x;
    if (i < NN) g_deg[i] = 0;
}

__global__ void count_deg_kernel(const int* __restrict__ ei_raw)
{
    int e = blockIdx.x * blockDim.x + threadIdx.x;
    if (e < EE) {
        int dst = load_edge(ei_raw, e, 1);
        if (dst >= 0 && dst < NN) atomicAdd(&g_deg[dst], 1);
    }
}

#define SCAN_BLKS ((NN + 255) / 256)
__global__ void scan1_kernel()
{
    __shared__ int sm[256];
    int i = blockIdx.x * 256 + threadIdx.x;
    sm[threadIdx.x] = (i < NN) ? g_deg[i] : 0;
    __syncthreads();
    for (int o = 128; o > 0; o >>= 1) {
        if (threadIdx.x < o) sm[threadIdx.x] += sm[threadIdx.x + o];
        __syncthreads();
    }
    if (threadIdx.x == 0) g_part[blockIdx.x] = sm[0];
}

__global__ void scan2_kernel()
{
    __shared__ int sm[256];
    int t = threadIdx.x;
    int v = (t < SCAN_BLKS) ? g_part[t] : 0;
    sm[t] = v;
    __syncthreads();
    for (int o = 1; o < 256; o <<= 1) {
        int u = (t >= o) ? sm[t - o] : 0;
        __syncthreads();
        sm[t] += u;
        __syncthreads();
    }
    if (t < SCAN_BLKS) g_part[t] = sm[t] - v;
    if (t == 255) g_off[NN] = sm[255];
}

__global__ void scan3_kernel()
{
    __shared__ int sm[256];
    int i = blockIdx.x * 256 + threadIdx.x;
    int v = (i < NN) ? g_deg[i] : 0;
    sm[threadIdx.x] = v;
    __syncthreads();
    for (int o = 1; o < 256; o <<= 1) {
        int u = (threadIdx.x >= o) ? sm[threadIdx.x - o] : 0;
        __syncthreads();
        sm[threadIdx.x] += u;
        __syncthreads();
    }
    if (i < NN) {
        int off = g_part[blockIdx.x] + sm[threadIdx.x] - v;
        g_off[i] = off;
        g_cur[i] = off;
    }
}

__global__ void scatter_kernel(const int* __restrict__ ei_raw)
{
    int e = blockIdx.x * blockDim.x + threadIdx.x;
    if (e < EE) {
        int src = load_edge(ei_raw, e, 0);
        int dst = load_edge(ei_raw, e, 1);
        if (src >= 0 && src < NN && dst >= 0 && dst < NN) {
            int pos = atomicAdd(&g_cur[dst], 1);
            if (pos >= 0 && pos < EE) g_src[pos] = src;
        }
    }
}

// ---------------- per-node online-softmax aggregation: one warp per node -------
// Depth-1 software pipeline (R8 configuration — measured best).
__global__ void agg_kernel(float* __restrict__ out)
{
    int warp = (blockIdx.x * blockDim.x + threadIdx.x) >> 5;
    int lane = threadIdx.x & 31;
    if (warp >= NN) return;

    const float* myq = g_qkvs + (size_t)warp * 512;
    const float4 q = *(const float4*)(myq + 4 * lane);

    const int s = g_off[warp];
    const int e = g_off[warp + 1];

    const float scale = 0.088388347648318447f;  // 1/sqrt(128)
    float m = -INFINITY, l = 0.f;
    float4 acc = make_float4(0.f, 0.f, 0.f, 0.f);

    if (e > s) {
        int src = g_src[s];
        const float* base = g_qkvs + (size_t)src * 512;
        float4 kk = *(const float4*)(base + 128 + 4 * lane);
        float4 vv = *(const float4*)(base + 256 + 4 * lane);

        for (int j = s; j < e; j++) {
            float4 kk_n, vv_n;
            if (j + 1 < e) {
                int src_n = g_src[j + 1];
                const float* base_n = g_qkvs + (size_t)src_n * 512;
                kk_n = *(const float4*)(base_n + 128 + 4 * lane);
                vv_n = *(const float4*)(base_n + 256 + 4 * lane);
            }

            float d = q.x * kk.x + q.y * kk.y + q.z * kk.z + q.w * kk.w;
            d += __shfl_xor_sync(0xffffffffu, d, 16);
            d += __shfl_xor_sync(0xffffffffu, d, 8);
            d += __shfl_xor_sync(0xffffffffu, d, 4);
            d += __shfl_xor_sync(0xffffffffu, d, 2);
            d += __shfl_xor_sync(0xffffffffu, d, 1);
            d *= scale;

            float newm = fmaxf(m, d);
            float fac = __expf(m - newm);
            float p   = __expf(d - newm);
            l = l * fac + p;

            acc.x = acc.x * fac + p * vv.x;
            acc.y = acc.y * fac + p * vv.y;
            acc.z = acc.z * fac + p * vv.z;
            acc.w = acc.w * fac + p * vv.w;
            m = newm;

            kk = kk_n;
            vv = vv_n;
        }
    }

    const float4 sk = *(const float4*)(myq + 384 + 4 * lane);
    float inv = (e > s) ? (1.f / l) : 0.f;
    float4 o;
    o.x = acc.x * inv + sk.x;
    o.y = acc.y * inv + sk.y;
    o.z = acc.z * inv + sk.z;
    o.w = acc.w * inv + sk.w;
    *(float4*)(out + (size_t)warp * DOUT + 4 * lane) = o;
}

// ---------------- launch --------------------------------------------------------
extern "C" void kernel_launch(void* const* d_in, const int* in_sizes, int n_in,
                              void* d_out, int out_size)
{
    const float* x    = (const float*)d_in[0];
    const int*   ei   = (const int*)d_in[1];
    const float* W_fc = (const float*)d_in[2];
    const float* b_fc = (const float*)d_in[3];
    const float* W_q  = (const float*)d_in[4];
    const float* b_q  = (const float*)d_in[5];
    const float* W_k  = (const float*)d_in[6];
    const float* b_k  = (const float*)d_in[7];
    const float* W_v  = (const float*)d_in[8];
    const float* b_v  = (const float*)d_in[9];
    const float* W_s  = (const float*)d_in[10];
    const float* b_s  = (const float*)d_in[11];
    float* out = (float*)d_out;

    static cudaStream_t s_side = nullptr;
    static cudaEvent_t ev_fork = nullptr, ev_join = nullptr;
    if (!s_side) {
        cudaStreamCreateWithFlags(&s_side, cudaStreamNonBlocking);
        cudaEventCreateWithFlags(&ev_fork, cudaEventDisableTiming);
        cudaEventCreateWithFlags(&ev_join, cudaEventDisableTiming);
        cudaFuncSetAttribute(fused_kernel, cudaFuncAttributeMaxDynamicSharedMemorySize,
                             SMEM_ELEMS * 2);
    }

    // dtype detection on main stream (R8 config), then fork side stream
    detect_dtype_kernel<<<1, 256>>>(ei);                              // submit #0
    cudaEventRecord(ev_fork, 0);
    cudaStreamWaitEvent(s_side, ev_fork, 0);

    // interleave submissions so fused_kernel is submission #3 (ncu capture slot);
    // stream/event deps keep execution identical to R8.
    zero_deg_kernel<<<(NN + 255) / 256, 256, 0, s_side>>>();          // submit #1 (side)
    conv_w2_kernel<<<(512 * DH / 2 + 255) / 256, 256>>>(W_q, b_q, W_k, b_k,
                                                        W_v, b_v, W_s, b_s);  // #2 (main)
    fused_kernel<<<(NN + 127) / 128, 256, SMEM_ELEMS * 2>>>(x, W_fc, b_fc);   // #3 (main)

    // rest of CSR chain on side stream
    count_deg_kernel<<<(EE + 255) / 256, 256, 0, s_side>>>(ei);       // #4
    scan1_kernel<<<SCAN_BLKS, 256, 0, s_side>>>();                    // #5
    scan2_kernel<<<1, 256, 0, s_side>>>();                            // #6
    scan3_kernel<<<SCAN_BLKS, 256, 0, s_side>>>();                    // #7
    scatter_kernel<<<(EE + 255) / 256, 256, 0, s_side>>>(ei);         // #8
    cudaEventRecord(ev_join, s_side);

    // join, then aggregate
    cudaStreamWaitEvent(0, ev_join, 0);
    agg_kernel<<<(NN * 32 + 255) / 256, 256>>>(out);                  // #9
}